// round 2
// baseline (speedup 1.0000x reference)
#include <cuda_runtime.h>

#define N_NODES 50000
#define F       128
#define NPB     32      // nodes per block in the fused GEMM
#define KT      32      // k-tile

// 25.6 MB scratch for the scatter-add aggregation (device global: no allocs allowed)
__device__ float g_agg[N_NODES * F];

// ---------------------------------------------------------------------------
// Kernel 1: zero the aggregation buffer (re-run every launch; graph replays)
// ---------------------------------------------------------------------------
__global__ void zero_agg_kernel() {
    int i = blockIdx.x * blockDim.x + threadIdx.x;
    const int n4 = N_NODES * F / 4;
    if (i < n4) {
        reinterpret_cast<float4*>(g_agg)[i] = make_float4(0.f, 0.f, 0.f, 0.f);
    }
}

// ---------------------------------------------------------------------------
// Kernel 2: edge scatter. One warp per edge: 32 lanes x float4 = 128 floats.
// Gather x[src] row (contiguous 512B per warp), vector-reduce into g_agg[dst].
// x fits in L2 (25.6MB) so gathers are L2 hits; red.v4 quarters atomic op count.
// NOTE: edge_index is int32 (JAX x64 disabled downcasts the requested int64).
// ---------------------------------------------------------------------------
__global__ void scatter_kernel(const float4* __restrict__ x4,
                               const int* __restrict__ src,
                               const int* __restrict__ dst,
                               int E) {
    int gtid = blockIdx.x * blockDim.x + threadIdx.x;
    int warp = gtid >> 5;
    int lane = threadIdx.x & 31;
    if (warp >= E) return;

    int s = src[warp];   // broadcast load (all lanes same address)
    int d = dst[warp];

    float4 v = x4[(long)s * 32 + lane];
    float* p = g_agg + ((long)d * F + lane * 4);
    asm volatile("red.global.add.v4.f32 [%0], {%1,%2,%3,%4};"
                 :: "l"(p), "f"(v.x), "f"(v.y), "f"(v.z), "f"(v.w)
                 : "memory");
}

// ---------------------------------------------------------------------------
// Kernel 3: fused dual GEMM + bias + ReLU.
// out[i,o] = relu( b[o] + sum_k agg[i,k]*Wrel[o,k] + sum_k x[i,k]*Wroot[o,k] )
//
// Block: 256 threads = 8 warps, 32 nodes. Warp w owns nodes base+4w..4w+3 and
// all 128 outputs (lane -> 4 consecutive output cols). Weights staged in smem
// transposed [k][o] with pad 132 so the float4 weight reads are bank-conflict
// free; input reads are warp-uniform broadcasts.
// ---------------------------------------------------------------------------
__global__ void __launch_bounds__(256)
gemm_relu_kernel(const float* __restrict__ x,
                 const float* __restrict__ Wrel,
                 const float* __restrict__ brel,
                 const float* __restrict__ Wroot,
                 float* __restrict__ out) {
    __shared__ float sWrel[KT][132];
    __shared__ float sWroot[KT][132];
    __shared__ float sA[NPB][36];
    __shared__ float sX[NPB][36];

    const int t    = threadIdx.x;       // 0..255
    const int warp = t >> 5;            // 0..7  -> node slot
    const int lane = t & 31;            // 0..31 -> output group
    const int o4   = lane * 4;          // first of 4 output cols
    const int nodeBase = blockIdx.x * NPB;

    float4 acc[4];
#pragma unroll
    for (int n = 0; n < 4; n++) acc[n] = make_float4(0.f, 0.f, 0.f, 0.f);

    for (int kc = 0; kc < F; kc += KT) {
        __syncthreads();

        // --- stage weights transposed: sW[kk][o] = W[o][kc+kk]
#pragma unroll
        for (int i = 0; i < (128 * KT) / 256; i++) {
            int idx = t + i * 256;
            int o  = idx >> 5;          // 0..127
            int kk = idx & 31;          // 0..31
            sWrel[kk][o]  = Wrel [o * F + kc + kk];
            sWroot[kk][o] = Wroot[o * F + kc + kk];
        }

        // --- stage inputs: 32 nodes x 32 k, float4 per thread
        {
            int node = t >> 3;          // 0..31
            int kq   = t & 7;           // 0..7 -> k offset kq*4
            int g    = nodeBase + node;
            int gc   = g < N_NODES ? g : N_NODES - 1;   // clamp (stores predicated)
            float4 a  = *reinterpret_cast<const float4*>(&g_agg[(long)gc * F + kc + kq * 4]);
            float4 xx = *reinterpret_cast<const float4*>(&x    [(long)gc * F + kc + kq * 4]);
            *reinterpret_cast<float4*>(&sA[node][kq * 4]) = a;
            *reinterpret_cast<float4*>(&sX[node][kq * 4]) = xx;
        }
        __syncthreads();

        // --- compute
#pragma unroll
        for (int kk = 0; kk < KT; kk++) {
            float4 wr = *reinterpret_cast<const float4*>(&sWrel[kk][o4]);
            float4 wo = *reinterpret_cast<const float4*>(&sWroot[kk][o4]);
#pragma unroll
            for (int n = 0; n < 4; n++) {
                float a  = sA[warp * 4 + n][kk];
                float xx = sX[warp * 4 + n][kk];
                acc[n].x += a * wr.x + xx * wo.x;
                acc[n].y += a * wr.y + xx * wo.y;
                acc[n].z += a * wr.z + xx * wo.z;
                acc[n].w += a * wr.w + xx * wo.w;
            }
        }
    }

    // --- epilogue: bias + relu + store
    float4 b4 = *reinterpret_cast<const float4*>(&brel[o4]);
#pragma unroll
    for (int n = 0; n < 4; n++) {
        int node = nodeBase + warp * 4 + n;
        if (node < N_NODES) {
            float4 r;
            r.x = fmaxf(acc[n].x + b4.x, 0.f);
            r.y = fmaxf(acc[n].y + b4.y, 0.f);
            r.z = fmaxf(acc[n].z + b4.z, 0.f);
            r.w = fmaxf(acc[n].w + b4.w, 0.f);
            reinterpret_cast<float4*>(out)[(long)node * (F / 4) + lane] = r;
        }
    }
}

// ---------------------------------------------------------------------------
extern "C" void kernel_launch(void* const* d_in, const int* in_sizes, int n_in,
                              void* d_out, int out_size) {
    const float* x     = (const float*)d_in[0];
    const int*   ei    = (const int*)d_in[1];     // int32! (JAX x64 disabled)
    const float* Wrel  = (const float*)d_in[2];
    const float* brel  = (const float*)d_in[3];
    const float* Wroot = (const float*)d_in[4];
    float*       out   = (float*)d_out;

    const int E = in_sizes[1] / 2;                // 800000
    const int* src = ei;
    const int* dst = ei + E;

    // 1) zero agg scratch
    {
        int n4 = N_NODES * F / 4;
        int blocks = (n4 + 255) / 256;
        zero_agg_kernel<<<blocks, 256>>>();
    }
    // 2) scatter-add: warp per edge
    {
        int blocks = (E + 7) / 8;   // 8 warps (edges) per 256-thread block
        scatter_kernel<<<blocks, 256>>>(
            reinterpret_cast<const float4*>(x), src, dst, E);
    }
    // 3) fused dual GEMM + bias + relu
    {
        int blocks = (N_NODES + NPB - 1) / NPB;
        gemm_relu_kernel<<<blocks, 256>>>(x, Wrel, brel, Wroot, out);
    }
}